// round 7
// baseline (speedup 1.0000x reference)
#include <cuda_runtime.h>
#include <cuda_bf16.h>
#include <cstdint>
#include <math.h>

#define Bz 4
#define Nz 2048
#define Dz 4096
#define Oz 4096
#define Rz 128
#define Ez 4
#define Pz 2

// ---------------- global scratch ----------------
__device__ __align__(16) unsigned g_bh[128*2048];   // basis hi  [128][4096]bf16 words
__device__ __align__(16) unsigned g_bl[128*2048];   // basis lo
__device__ __align__(16) unsigned g_wh[4096*64];    // W^T hi    [4096][128]bf16 words
__device__ __align__(16) unsigned g_wl[4096*64];
__device__ __align__(16) float    g_pp0[8192*128];  // proj partial (ksplit 0) fp32
__device__ __align__(16) float    g_pp1[8192*128];  // proj partial (ksplit 1)
__device__ __align__(16) unsigned g_dh[8192*64];    // delta hi [8192][128]bf16 words
__device__ __align__(16) unsigned g_dl[8192*64];
__device__ __align__(16) unsigned g_abth[4*128*64]; // A_b^T hi [b][n=128][r word]
__device__ __align__(16) unsigned g_abtl[4*128*64];

// ---------------- helpers ----------------
__device__ __forceinline__ unsigned short bfbits(float f){
    unsigned short u; asm("cvt.rn.bf16.f32 %0, %1;" : "=h"(u) : "f"(f)); return u;
}
__device__ __forceinline__ float bf2f(unsigned short u){
    return __uint_as_float(((unsigned)u)<<16);
}
__device__ __forceinline__ void split2(float a, float b, unsigned &hi, unsigned &lo){
    unsigned short ha=bfbits(a), hb=bfbits(b);
    hi = (unsigned)ha | ((unsigned)hb<<16);
    unsigned short la=bfbits(a - bf2f(ha)), lb=bfbits(b - bf2f(hb));
    lo = (unsigned)la | ((unsigned)lb<<16);
}
__device__ __forceinline__ unsigned smem_u32(const void* p){
    unsigned a; asm("{ .reg .u64 t; cvta.to.shared.u64 t, %1; cvt.u32.u64 %0, t; }" : "=r"(a) : "l"(p));
    return a;
}
__device__ __forceinline__ void mma16816(float d[4], const unsigned a[4], const unsigned b[2]){
    asm volatile("mma.sync.aligned.m16n8k16.row.col.f32.bf16.bf16.f32 "
        "{%0,%1,%2,%3}, {%4,%5,%6,%7}, {%8,%9}, {%0,%1,%2,%3};"
        : "+f"(d[0]), "+f"(d[1]), "+f"(d[2]), "+f"(d[3])
        : "r"(a[0]), "r"(a[1]), "r"(a[2]), "r"(a[3]), "r"(b[0]), "r"(b[1]));
}
__device__ __forceinline__ void ldsm4(unsigned r[4], unsigned addr){
    asm volatile("ldmatrix.sync.aligned.m8n8.x4.shared.b16 {%0,%1,%2,%3}, [%4];"
        : "=r"(r[0]), "=r"(r[1]), "=r"(r[2]), "=r"(r[3]) : "r"(addr));
}
__device__ __forceinline__ void cpasync16(unsigned saddr, const void* gp){
    asm volatile("cp.async.cg.shared.global [%0], [%1], 16;" :: "r"(saddr), "l"(gp));
}
#define CP_COMMIT() asm volatile("cp.async.commit_group;" ::: "memory")
#define CP_WAIT(n)  asm volatile("cp.async.wait_group %0;" :: "n"(n) : "memory")

// one k-step: 8 ldmatrix.x4 + 24 HMMA (products hh, h*bl, al*bh)
// a0/a1: hi-plane A tile addrs (mt 0/1); b0/b1: hi-plane B tile addrs (nt-pair 0/1)
__device__ __forceinline__ void kstep24(float acc[2][4][4],
    unsigned a0, unsigned a1, unsigned b0, unsigned b1,
    unsigned aloB, unsigned bloB)
{
    unsigned ah0[4],ah1[4],al0[4],al1[4],bh0[4],bh1[4],bl0[4],bl1[4];
    ldsm4(ah0,a0); ldsm4(ah1,a1); ldsm4(al0,a0+aloB); ldsm4(al1,a1+aloB);
    ldsm4(bh0,b0); ldsm4(bh1,b1); ldsm4(bl0,b0+bloB); ldsm4(bl1,b1+bloB);
    mma16816(acc[0][0],ah0,bh0);   mma16816(acc[0][1],ah0,bh0+2);
    mma16816(acc[0][2],ah0,bh1);   mma16816(acc[0][3],ah0,bh1+2);
    mma16816(acc[1][0],ah1,bh0);   mma16816(acc[1][1],ah1,bh0+2);
    mma16816(acc[1][2],ah1,bh1);   mma16816(acc[1][3],ah1,bh1+2);
    mma16816(acc[0][0],ah0,bl0);   mma16816(acc[0][1],ah0,bl0+2);
    mma16816(acc[0][2],ah0,bl1);   mma16816(acc[0][3],ah0,bl1+2);
    mma16816(acc[1][0],ah1,bl0);   mma16816(acc[1][1],ah1,bl0+2);
    mma16816(acc[1][2],ah1,bl1);   mma16816(acc[1][3],ah1,bl1+2);
    mma16816(acc[0][0],al0,bh0);   mma16816(acc[0][1],al0,bh0+2);
    mma16816(acc[0][2],al0,bh1);   mma16816(acc[0][3],al0,bh1+2);
    mma16816(acc[1][0],al1,bh0);   mma16816(acc[1][1],al1,bh0+2);
    mma16816(acc[1][2],al1,bh1);   mma16816(acc[1][3],al1,bh1+2);
}

// ---------------------------------------------------------------------------
// setup: A_b^T[n][r] words, bf16 hi/lo
// ---------------------------------------------------------------------------
__global__ __launch_bounds__(256) void setup_kernel(
    const float* __restrict__ logits, const float* __restrict__ mask,
    const float* __restrict__ gains,  const float* __restrict__ refl)
{
    __shared__ float s_v[Ez*Pz*Rz];
    __shared__ float s_inorm[Ez*Pz];
    __shared__ float s_c[Ez], s_ew[Ez], s_m[Rz], s_g[Ez*Rz];
    const int b = blockIdx.x;
    const int tid = threadIdx.x;

    for (int i = tid; i < Ez*Pz*Rz; i += 256) s_v[i] = refl[i];
    for (int i = tid; i < Rz; i += 256) s_m[i] = mask[b*Rz + i];
    for (int i = tid; i < Ez*Rz; i += 256) s_g[i] = gains[b*Ez*Rz + i];
    __syncthreads();
    if (tid < Ez*Pz) {
        float ss = 0.f;
        const float* v = s_v + tid*Rz;
        for (int r = 0; r < Rz; r++) ss += v[r]*v[r];
        s_inorm[tid] = 1.f / fmaxf(sqrtf(ss), 1e-6f);
    }
    __syncthreads();
    for (int i = tid; i < Ez*Pz*Rz; i += 256) s_v[i] *= s_inorm[i >> 7];
    __syncthreads();
    if (tid < Ez) {
        float c = 0.f;
        const float* v0 = s_v + (tid*Pz+0)*Rz;
        const float* v1 = s_v + (tid*Pz+1)*Rz;
        for (int r = 0; r < Rz; r++) c += v0[r]*v1[r];
        s_c[tid] = c;
    }
    if (tid == 0) {
        float m = -1e30f;
        for (int e = 0; e < Ez; e++) m = fmaxf(m, logits[b*Ez + e]);
        float t[Ez], s = 0.f;
        for (int e = 0; e < Ez; e++) { t[e] = expf(2.f*(logits[b*Ez+e]-m)); s += t[e]; }
        for (int e = 0; e < Ez; e++) s_ew[e] = t[e] / s;
    }
    __syncthreads();

    for (int j = 0; j < 32; j++) {
        const int idx = tid + j*256;
        const int n = idx >> 6;
        const int t = idx & 63;
        float val[2];
        #pragma unroll
        for (int q = 0; q < 2; q++) {
            const int r = 2*t + q;
            const float del = (r == n) ? 1.f : 0.f;
            float sum = 0.f;
            #pragma unroll
            for (int e = 0; e < Ez; e++) {
                const float v0r = s_v[(e*Pz+0)*Rz + r], v0n = s_v[(e*Pz+0)*Rz + n];
                const float v1r = s_v[(e*Pz+1)*Rz + r], v1n = s_v[(e*Pz+1)*Rz + n];
                const float chart = del - 2.f*v0r*v0n - 2.f*v1r*v1n + 4.f*s_c[e]*v1r*v0n;
                sum += s_ew[e] * s_g[e*Rz + n] * chart;
            }
            val[q] = s_m[r] * (sum - del);
        }
        unsigned hi, lo; split2(val[0], val[1], hi, lo);
        g_abth[b*8192 + n*64 + t] = hi;
        g_abtl[b*8192 + n*64 + t] = lo;
    }
}

// ---------------------------------------------------------------------------
__global__ __launch_bounds__(256) void conv_basis_kernel(const float* __restrict__ bas)
{
    const int idx4 = blockIdx.x*256 + threadIdx.x;
    const float4 v = ((const float4*)bas)[idx4];
    unsigned h0,l0,h1,l1;
    split2(v.x, v.y, h0, l0);
    split2(v.z, v.w, h1, l1);
    ((uint2*)g_bh)[idx4] = make_uint2(h0, h1);
    ((uint2*)g_bl)[idx4] = make_uint2(l0, l1);
}

__global__ __launch_bounds__(256) void conv_w_kernel(const float* __restrict__ w)
{
    __shared__ float s_in[128*68];
    const int tid = threadIdx.x;
    const int n0 = blockIdx.x * 64;
    #pragma unroll
    for (int t = 0; t < 8; t++) {
        const int idx = tid + t*256;
        const int row = idx >> 4;
        const int seg = idx & 15;
        *(float4*)&s_in[row*68 + seg*4] = *(const float4*)(w + (long)row*Oz + n0 + seg*4);
    }
    __syncthreads();
    #pragma unroll
    for (int t8 = 0; t8 < 16; t8++) {
        const int idx = tid + t8*256;
        const int n = idx >> 6;
        const int t = idx & 63;
        unsigned hi, lo;
        split2(s_in[(2*t)*68 + n], s_in[(2*t+1)*68 + n], hi, lo);
        g_wh[(long)(n0+n)*64 + t] = hi;
        g_wl[(long)(n0+n)*64 + t] = lo;
    }
}

// ---------------------------------------------------------------------------
// GEMM1: partial proj (K-split 2). grid 256 = 128 mtiles x 2 ks. 2 CTAs/SM.
// smem: A (64x72 hi + lo) 18432B @0 ; B 2 bufs of (128x72 hi + lo) 36864B @18432
// ---------------------------------------------------------------------------
#define G1_ALO   9216u
#define G1_BOFF  18432u
#define G1_BBUF  36864u
#define G1_BLO   18432u
#define G1_SMEM  92160

__global__ __launch_bounds__(256,2) void gemm1_kernel(const float* __restrict__ x)
{
    extern __shared__ unsigned short sm[];
    const unsigned sbase = smem_u32(sm);
    const int tid = threadIdx.x;
    const int wid = tid >> 5, lane = tid & 31;
    const int wm = wid & 1, wn = wid >> 1;
    const int g = lane >> 2, tig = lane & 3;
    const int mtile = blockIdx.x >> 1;
    const int ks = blockIdx.x & 1;
    const long m0 = (long)mtile * 64;
    const int c0 = ks * 32;                   // starting k-chunk (64 wide)

    float acc[2][4][4];
    #pragma unroll
    for (int mt = 0; mt < 2; mt++)
        #pragma unroll
        for (int nt = 0; nt < 4; nt++)
            #pragma unroll
            for (int q = 0; q < 4; q++) acc[mt][nt][q] = 0.f;

    // ldmatrix lane addressing
    const int sub = lane >> 3, r8 = lane & 7;
    const unsigned aoff = (unsigned)(((r8 + ((sub&1)<<3))*72 + ((sub>>1)<<3)) * 2);
    const unsigned boff = (unsigned)(((r8 + ((sub>>1)<<3))*72 + ((sub&1)<<3)) * 2);
    const unsigned aA0 = sbase + (unsigned)(wm*32*144) + aoff;
    const unsigned aA1 = aA0 + 16*144;
    const unsigned bB0r = G1_BOFF + (unsigned)(wn*32*144) + boff;   // relative to sbase+buf
    const unsigned bB1r = bB0r + 16*144;

    // x geometry: 64 rows x 16 float4
    const int xrow = tid >> 4, xseg = tid & 15;
    const float* xbase = x + (m0 + xrow)*Dz + (long)c0*64 + xseg*4;
    float4 xr[4];
    #pragma unroll
    for (int t = 0; t < 4; t++) xr[t] = *(const float4*)(xbase + (t*16)*Dz);

    // B cp.async geometry: per chunk 128 rows x 8 segs (hi + lo)
    const int brow = tid >> 1;               // 0..127
    const int bs2  = (tid & 1) << 2;         // seg base 0 or 4
    {
        const unsigned sB = sbase + G1_BOFF;
        #pragma unroll
        for (int s = 0; s < 4; s++) {
            cpasync16(sB + (unsigned)(brow*144 + (bs2+s)*16),
                      g_bh + (long)brow*2048 + c0*32 + (bs2+s)*4);
            cpasync16(sB + G1_BLO + (unsigned)(brow*144 + (bs2+s)*16),
                      g_bl + (long)brow*2048 + c0*32 + (bs2+s)*4);
        }
        CP_COMMIT();
    }

    for (int ci = 0; ci < 32; ci++) {
        const int buf = ci & 1;
        if (ci < 31) {
            const unsigned sB = sbase + G1_BOFF + (unsigned)((buf^1))*G1_BBUF;
            const int c = c0 + ci + 1;
            #pragma unroll
            for (int s = 0; s < 4; s++) {
                cpasync16(sB + (unsigned)(brow*144 + (bs2+s)*16),
                          g_bh + (long)brow*2048 + c*32 + (bs2+s)*4);
                cpasync16(sB + G1_BLO + (unsigned)(brow*144 + (bs2+s)*16),
                          g_bl + (long)brow*2048 + c*32 + (bs2+s)*4);
            }
            CP_COMMIT();
        }
        // store A chunk ci (prev mma finished at trailing sync)
        #pragma unroll
        for (int t = 0; t < 4; t++) {
            const int row = xrow + t*16;
            unsigned h0,l0,h1,l1;
            split2(xr[t].x, xr[t].y, h0, l0);
            split2(xr[t].z, xr[t].w, h1, l1);
            *(uint2*)((char*)sm + row*144 + xseg*8)           = make_uint2(h0, h1);
            *(uint2*)((char*)sm + G1_ALO + row*144 + xseg*8)  = make_uint2(l0, l1);
        }
        if (ci < 31) {
            #pragma unroll
            for (int t = 0; t < 4; t++) xr[t] = *(const float4*)(xbase + (t*16)*Dz + (ci+1)*64);
        }
        if (ci < 31) CP_WAIT(1); else CP_WAIT(0);
        __syncthreads();

        const unsigned bbase = sbase + (unsigned)buf*G1_BBUF;
        #pragma unroll
        for (int kst = 0; kst < 4; kst++) {
            kstep24(acc, aA0 + kst*32, aA1 + kst*32,
                    bbase + bB0r + kst*32, bbase + bB1r + kst*32,
                    G1_ALO, G1_BLO);
        }
        __syncthreads();
    }

    float* pp = ks ? g_pp1 : g_pp0;
    #pragma unroll
    for (int mt = 0; mt < 2; mt++)
        #pragma unroll
        for (int nt = 0; nt < 4; nt++) {
            const long r0 = m0 + wm*32 + mt*16 + g;
            const int col = wn*32 + nt*8 + 2*tig;
            *(float2*)&pp[r0*128 + col]     = make_float2(acc[mt][nt][0], acc[mt][nt][1]);
            *(float2*)&pp[(r0+8)*128 + col] = make_float2(acc[mt][nt][2], acc[mt][nt][3]);
        }
}

// ---------------------------------------------------------------------------
// delta: sum partials -> split -> mma vs A_b^T -> g_dh/g_dl. grid 128 (m64).
// smem: A (64x136 hi+lo) 34816B @0 ; B (128x136 hi+lo) 69632B @34816
// ---------------------------------------------------------------------------
#define D_ALO   17408u
#define D_BOFF  34816u
#define D_BLO   34816u
#define D_SMEM  104448

__global__ __launch_bounds__(256,2) void delta_kernel()
{
    extern __shared__ unsigned short sm[];
    const unsigned sbase = smem_u32(sm);
    const int tid = threadIdx.x;
    const int wid = tid >> 5, lane = tid & 31;
    const int wm = wid & 1, wn = wid >> 1;
    const int g = lane >> 2, tig = lane & 3;
    const int mtile = blockIdx.x;
    const long m0 = (long)mtile * 64;
    const int b = mtile >> 5;

    // B: cp.async abt tile (128 rows x 16 segs, hi+lo)
    #pragma unroll
    for (int j = 0; j < 8; j++) {
        const int idx = tid + j*256;
        const int row = idx >> 4, seg = idx & 15;
        const unsigned dst = sbase + D_BOFF + (unsigned)(row*272 + seg*16);
        cpasync16(dst,          g_abth + (long)b*8192 + row*64 + seg*4);
        cpasync16(dst + D_BLO,  g_abtl + (long)b*8192 + row*64 + seg*4);
    }
    CP_COMMIT();

    // A: sum fp32 partials, split -> smem
    #pragma unroll
    for (int j = 0; j < 8; j++) {
        const int idx = tid + j*256;        // 2048 float4 = 64 rows x 32
        const int row = idx >> 5, seg = idx & 31;
        const long go = (m0 + row)*128 + seg*4;
        const float4 u = *(const float4*)(g_pp0 + go);
        const float4 v = *(const float4*)(g_pp1 + go);
        unsigned h0,l0,h1,l1;
        split2(u.x + v.x, u.y + v.y, h0, l0);
        split2(u.z + v.z, u.w + v.w, h1, l1);
        *(uint2*)((char*)sm + row*272 + seg*8)          = make_uint2(h0, h1);
        *(uint2*)((char*)sm + D_ALO + row*272 + seg*8)  = make_uint2(l0, l1);
    }
    CP_WAIT(0);
    __syncthreads();

    float acc[2][4][4];
    #pragma unroll
    for (int mt = 0; mt < 2; mt++)
        #pragma unroll
        for (int nt = 0; nt < 4; nt++)
            #pragma unroll
            for (int q = 0; q < 4; q++) acc[mt][nt][q] = 0.f;

    const int sub = lane >> 3, r8 = lane & 7;
    const unsigned aoff = (unsigned)(((r8 + ((sub&1)<<3))*136 + ((sub>>1)<<3)) * 2);
    const unsigned boff = (unsigned)(((r8 + ((sub>>1)<<3))*136 + ((sub&1)<<3)) * 2);
    const unsigned aA0 = sbase + (unsigned)(wm*32*272) + aoff;
    const unsigned aA1 = aA0 + 16*272;
    const unsigned aB0 = sbase + D_BOFF + (unsigned)(wn*32*272) + boff;
    const unsigned aB1 = aB0 + 16*272;

    #pragma unroll
    for (int kst = 0; kst < 8; kst++)
        kstep24(acc, aA0 + kst*32, aA1 + kst*32, aB0 + kst*32, aB1 + kst*32, D_ALO, D_BLO);

    #pragma unroll
    for (int mt = 0; mt < 2; mt++)
        #pragma unroll
        for (int nt = 0; nt < 4; nt++) {
            const long r0 = m0 + wm*32 + mt*16 + g;
            const int col2 = wn*16 + nt*4 + tig;
            unsigned hi, lo;
            split2(acc[mt][nt][0], acc[mt][nt][1], hi, lo);
            g_dh[r0*64 + col2] = hi; g_dl[r0*64 + col2] = lo;
            split2(acc[mt][nt][2], acc[mt][nt][3], hi, lo);
            g_dh[(r0+8)*64 + col2] = hi; g_dl[(r0+8)*64 + col2] = lo;
        }
}

// ---------------------------------------------------------------------------
// GEMM2: out = delta @ W via wT. grid (64 n, 64 m): m128 x n64. 2 CTAs/SM.
// smem: A (128x136 hi+lo) 69632B @0 ; B (64x136 hi+lo) 34816B @69632
// ---------------------------------------------------------------------------
#define H_ALO   34816u
#define H_BOFF  69632u
#define H_BLO   17408u
#define H_SMEM  104448

__global__ __launch_bounds__(256,2) void gemm2_kernel(float* __restrict__ out)
{
    extern __shared__ unsigned short sm[];
    const unsigned sbase = smem_u32(sm);
    const int tid = threadIdx.x;
    const int wid = tid >> 5, lane = tid & 31;
    const int wm = wid & 3, wn = wid >> 2;
    const int g = lane >> 2, tig = lane & 3;
    const long m0 = (long)blockIdx.y * 128;
    const long n0 = (long)blockIdx.x * 64;

    // A: 128 rows x 16 segs (hi+lo) = 4096 cp.async
    #pragma unroll
    for (int j = 0; j < 8; j++) {
        const int idx = tid + j*256;
        const int row = idx >> 4, seg = idx & 15;
        const unsigned dst = sbase + (unsigned)(row*272 + seg*16);
        cpasync16(dst,          g_dh + (m0 + row)*64 + seg*4);
        cpasync16(dst + H_ALO,  g_dl + (m0 + row)*64 + seg*4);
    }
    // B: 64 rows x 16 segs (hi+lo) = 2048 cp.async
    #pragma unroll
    for (int j = 0; j < 4; j++) {
        const int idx = tid + j*256;
        const int row = idx >> 4, seg = idx & 15;
        const unsigned dst = sbase + H_BOFF + (unsigned)(row*272 + seg*16);
        cpasync16(dst,          g_wh + (n0 + row)*64 + seg*4);
        cpasync16(dst + H_BLO,  g_wl + (n0 + row)*64 + seg*4);
    }
    CP_COMMIT();
    CP_WAIT(0);
    __syncthreads();

    float acc[2][4][4];
    #pragma unroll
    for (int mt = 0; mt < 2; mt++)
        #pragma unroll
        for (int nt = 0; nt < 4; nt++)
            #pragma unroll
            for (int q = 0; q < 4; q++) acc[mt][nt][q] = 0.f;

    const int sub = lane >> 3, r8 = lane & 7;
    const unsigned aoff = (unsigned)(((r8 + ((sub&1)<<3))*136 + ((sub>>1)<<3)) * 2);
    const unsigned boff = (unsigned)(((r8 + ((sub>>1)<<3))*136 + ((sub&1)<<3)) * 2);
    const unsigned aA0 = sbase + (unsigned)(wm*32*272) + aoff;
    const unsigned aA1 = aA0 + 16*272;
    const unsigned aB0 = sbase + H_BOFF + (unsigned)(wn*32*272) + boff;
    const unsigned aB1 = aB0 + 16*272;

    #pragma unroll
    for (int kst = 0; kst < 8; kst++)
        kstep24(acc, aA0 + kst*32, aA1 + kst*32, aB0 + kst*32, aB1 + kst*32, H_ALO, H_BLO);

    __syncthreads();   // frags consumed; reuse smem for fp32 out staging
    float* s_out = (float*)sm;   // 128 x 68 floats
    #pragma unroll
    for (int mt = 0; mt < 2; mt++)
        #pragma unroll
        for (int nt = 0; nt < 4; nt++) {
            const int lr = wm*32 + mt*16 + g;
            const int lc = wn*32 + nt*8 + 2*tig;
            *(float2*)&s_out[lr*68 + lc]     = make_float2(acc[mt][nt][0], acc[mt][nt][1]);
            *(float2*)&s_out[(lr+8)*68 + lc] = make_float2(acc[mt][nt][2], acc[mt][nt][3]);
        }
    __syncthreads();
    #pragma unroll
    for (int j = 0; j < 8; j++) {
        const int idx = tid + j*256;        // 2048 float4 = 128 rows x 16
        const int row = idx >> 4, seg = idx & 15;
        *(float4*)(out + (m0 + row)*Oz + n0 + seg*4) = *(const float4*)&s_out[row*68 + seg*4];
    }
}

// ---------------------------------------------------------------------------
extern "C" void kernel_launch(void* const* d_in, const int* in_sizes, int n_in,
                              void* d_out, int out_size)
{
    const float* x      = (const float*)d_in[0];
    const float* logits = (const float*)d_in[1];
    const float* mask   = (const float*)d_in[2];
    const float* gains  = (const float*)d_in[3];
    const float* ibasis = (const float*)d_in[4];
    const float* obasis = (const float*)d_in[5];
    const float* refl   = (const float*)d_in[6];
    float* out = (float*)d_out;

    cudaFuncSetAttribute(gemm1_kernel, cudaFuncAttributeMaxDynamicSharedMemorySize, G1_SMEM);
    cudaFuncSetAttribute(delta_kernel, cudaFuncAttributeMaxDynamicSharedMemorySize, D_SMEM);
    cudaFuncSetAttribute(gemm2_kernel, cudaFuncAttributeMaxDynamicSharedMemorySize, H_SMEM);

    setup_kernel<<<Bz, 256>>>(logits, mask, gains, refl);
    conv_basis_kernel<<<512, 256>>>(ibasis);
    conv_w_kernel<<<64, 256>>>(obasis);
    gemm1_kernel<<<256, 256, G1_SMEM>>>(x);
    delta_kernel<<<128, 256, D_SMEM>>>();
    gemm2_kernel<<<dim3(64, 64), 256, H_SMEM>>>(out);
}